// round 10
// baseline (speedup 1.0000x reference)
#include <cuda_runtime.h>
#include <cuda_fp16.h>
#include <cstdint>

#define B_DIM 8192
#define F_DIM 64
#define NXX   82
#define NYY   67
#define P_DIM (NXX * NYY)   // 5494
#define NPAD  5504          // 86 * 64

#define BM 128
#define BN 64
#define GEMM_THREADS 256

// Scratch: permuted (transpose-folded) W in fp16, permuted bias in fp32.
__device__ __half g_Wp[NPAD * F_DIM];
__device__ float  g_bp[NPAD];

// Pack two floats into a half2 register (uint32), rn rounding.
__device__ __forceinline__ uint32_t pack_half2(float x, float y) {
    uint32_t r;
    asm("{ .reg .f16 lo, hi;\n\t"
        "  cvt.rn.f16.f32 lo, %1;\n\t"
        "  cvt.rn.f16.f32 hi, %2;\n\t"
        "  mov.b32 %0, {lo, hi}; }"
        : "=r"(r) : "f"(x), "f"(y));
    return r;
}

// Fold the output transpose into W: W'[q][f] = W[p][f], q = x*67+y, p = y*82+x.
__global__ void permute_kernel(const float* __restrict__ W,
                               const float* __restrict__ bias) {
    int idx = blockIdx.x * blockDim.x + threadIdx.x;
    if (idx >= NPAD * F_DIM) return;
    int q = idx >> 6;
    int f = idx & 63;
    float v = 0.0f;
    if (q < P_DIM) {
        int x = q / NYY;
        int y = q - x * NYY;
        int p = y * NXX + x;
        v = W[p * F_DIM + f];
    }
    g_Wp[idx] = __float2half_rn(v);
    if (f == 0) {
        float bb = 0.0f;
        if (q < P_DIM) {
            int x = q / NYY;
            int y = q - x * NYY;
            bb = bias[y * NXX + x];
        }
        g_bp[q] = bb;
    }
}

// C[b][q] = sum_f A[b][f] * W'[q][f] + bias'[q]; out [B, 5494] contiguous.
// fp16 m16n8k16 MMA. Block 128x64, K=64 (4 k-blocks). 8 warps 4(m)x2(n),
// warp tile 32x32. Smem rows are 64 halves = 128B; XOR swizzle on 16B groups.
__global__ __launch_bounds__(GEMM_THREADS, 3)
void gemm_kernel(const float* __restrict__ A, float* __restrict__ out) {
    __shared__ uint32_t Asm[BM * 32];   // 16 KB (half2 units, 32 per row)
    __shared__ uint32_t Bsm[BN * 32];   //  8 KB

    const int tid = threadIdx.x;
    const int bn0 = blockIdx.x * BN;   // n fast -> concurrent blocks share A in L2
    const int bm0 = blockIdx.y * BM;

    {
        const int c4 = tid & 15;   // 16B (gmem) / 8B (smem) column, 0..15
        const int r0 = tid >> 4;   // 16 rows per pass
        // A: fp32 -> fp16 convert while staging
        const float4* Ag = (const float4*)(A + (size_t)bm0 * 64);
        uint2* Asm2 = (uint2*)Asm;
        #pragma unroll
        for (int i = 0; i < BM / 16; i++) {
            int r = r0 + i * 16;
            float4 v = Ag[r * 16 + c4];
            uint2 h;
            h.x = pack_half2(v.x, v.y);
            h.y = pack_half2(v.z, v.w);
            int g = (c4 >> 1) ^ (r & 7);
            Asm2[r * 16 + (g << 1) + (c4 & 1)] = h;
        }
        // B: already fp16 in g_Wp
        const uint2* Bg = (const uint2*)(g_Wp + (size_t)bn0 * 64);
        uint2* Bsm2 = (uint2*)Bsm;
        #pragma unroll
        for (int i = 0; i < BN / 16; i++) {
            int r = r0 + i * 16;
            uint2 v = Bg[r * 16 + c4];
            int g = (c4 >> 1) ^ (r & 7);
            Bsm2[r * 16 + (g << 1) + (c4 & 1)] = v;
        }
    }
    __syncthreads();

    const int warp = tid >> 5;
    const int lane = tid & 31;
    const int wm = (warp & 3) * 32;     // 4 warps along m
    const int wn = (warp >> 2) * 32;    // 2 warps along n
    const int lrow = lane >> 2;         // groupID, 0..7
    const int lcol = lane & 3;          // threadID_in_group

    float acc[2][4][4];
    #pragma unroll
    for (int i = 0; i < 2; i++)
        #pragma unroll
        for (int j = 0; j < 4; j++)
            #pragma unroll
            for (int k = 0; k < 4; k++) acc[i][j][k] = 0.0f;

    #pragma unroll
    for (int kb = 0; kb < 4; kb++) {           // k-blocks of 16
        const int g0 = (2 * kb)     ^ lrow;    // 16B-group, low half of k-block
        const int g1 = (2 * kb + 1) ^ lrow;    // high half
        uint32_t a[2][4];
        #pragma unroll
        for (int mf = 0; mf < 2; mf++) {
            int ra = wm + mf * 16 + lrow;      // ra&7 == lrow
            int rb = ra + 8;
            a[mf][0] = Asm[ra * 32 + (g0 << 2) + lcol];
            a[mf][1] = Asm[rb * 32 + (g0 << 2) + lcol];
            a[mf][2] = Asm[ra * 32 + (g1 << 2) + lcol];
            a[mf][3] = Asm[rb * 32 + (g1 << 2) + lcol];
        }
        uint32_t b[4][2];
        #pragma unroll
        for (int nf = 0; nf < 4; nf++) {
            int rn = wn + nf * 8 + lrow;       // rn&7 == lrow
            b[nf][0] = Bsm[rn * 32 + (g0 << 2) + lcol];
            b[nf][1] = Bsm[rn * 32 + (g1 << 2) + lcol];
        }
        #pragma unroll
        for (int mf = 0; mf < 2; mf++) {
            #pragma unroll
            for (int nf = 0; nf < 4; nf++) {
                asm volatile(
                    "mma.sync.aligned.m16n8k16.row.col.f32.f16.f16.f32 "
                    "{%0,%1,%2,%3}, {%4,%5,%6,%7}, {%8,%9}, {%0,%1,%2,%3};\n"
                    : "+f"(acc[mf][nf][0]), "+f"(acc[mf][nf][1]),
                      "+f"(acc[mf][nf][2]), "+f"(acc[mf][nf][3])
                    : "r"(a[mf][0]), "r"(a[mf][1]), "r"(a[mf][2]), "r"(a[mf][3]),
                      "r"(b[nf][0]), "r"(b[nf][1]));
            }
        }
    }

    // Epilogue: bias + coalesced stores (q contiguous in output).
    const int q0 = bn0 + wn + 2 * lcol;
    #pragma unroll
    for (int mf = 0; mf < 2; mf++) {
        int grow = bm0 + wm + mf * 16 + lrow;
        #pragma unroll
        for (int nf = 0; nf < 4; nf++) {
            int q = q0 + nf * 8;
            if (q < P_DIM) {
                float bq0 = g_bp[q];
                float bq1 = g_bp[q + 1];
                float2 v0 = make_float2(acc[mf][nf][0] + bq0, acc[mf][nf][1] + bq1);
                float2 v1 = make_float2(acc[mf][nf][2] + bq0, acc[mf][nf][3] + bq1);
                *(float2*)&out[(size_t)grow * P_DIM + q] = v0;
                *(float2*)&out[(size_t)(grow + 8) * P_DIM + q] = v1;
            }
        }
    }
}

extern "C" void kernel_launch(void* const* d_in, const int* in_sizes, int n_in,
                              void* d_out, int out_size) {
    const float* inputs = (const float*)d_in[0];   // [8192, 64]
    const float* W      = (const float*)d_in[1];   // [5494, 64]
    const float* bias   = (const float*)d_in[2];   // [5494]
    float* out = (float*)d_out;                    // [8192, 82, 67, 1]

    (void)in_sizes; (void)n_in; (void)out_size;

    int pthreads = 256;
    int pblocks = (NPAD * F_DIM + pthreads - 1) / pthreads;
    permute_kernel<<<pblocks, pthreads>>>(W, bias);

    dim3 grid(NPAD / BN, B_DIM / BM);   // (86, 64)
    gemm_kernel<<<grid, GEMM_THREADS>>>(inputs, out);
}

// round 14
// speedup vs baseline: 1.1888x; 1.1888x over previous
#include <cuda_runtime.h>
#include <cstdint>

#define B_DIM 8192
#define F_DIM 64
#define NXX   82
#define NYY   67
#define P_DIM (NXX * NYY)   // 5494
#define NPAD  5504          // 86 * 64

#define BM 128
#define BN 64
#define GEMM_THREADS 256

__device__ __forceinline__ uint32_t f2tf32(float x) {
    uint32_t r;
    asm("cvt.rna.tf32.f32 %0, %1;" : "=r"(r) : "f"(x));
    return r;
}

// C[b][q] = sum_f A[b][f] * W[p(q)][f] + bias[p(q)], where q = x*67+y,
// p = y*82+x (output transpose folded into a B-row gather — a full 256B W row
// per tile row, so gather granularity == warp load granularity: no extra cost).
// out is [B, 5494] contiguous. Block 128x64, K=64 single pass, 8 warps 4(m)x2(n),
// warp tile 32x32 of m16n8k8 tf32.
__global__ __launch_bounds__(GEMM_THREADS, 4)
void gemm_kernel(const float* __restrict__ A, const float* __restrict__ W,
                 const float* __restrict__ bias, float* __restrict__ out) {
    __shared__ uint32_t Asm[BM * 64];   // 32 KB
    __shared__ uint32_t Bsm[BN * 64];   // 16 KB

    const int tid = threadIdx.x;
    const int bn0 = blockIdx.x * BN;   // n fast -> concurrent blocks share A in L2
    const int bm0 = blockIdx.y * BM;

    {
        const int c4 = tid & 15;   // float4 column
        const int r0 = tid >> 4;   // 16 rows per pass
        const float4* Ag = (const float4*)(A + (size_t)bm0 * 64);
        #pragma unroll
        for (int i = 0; i < BM / 16; i++) {
            int r = r0 + i * 16;
            float4 v = Ag[r * 16 + c4];
            int pc4 = c4 ^ (r & 7);
            uint4 t;
            t.x = f2tf32(v.x); t.y = f2tf32(v.y);
            t.z = f2tf32(v.z); t.w = f2tf32(v.w);
            *(uint4*)&Asm[r * 64 + pc4 * 4] = t;
        }
        // B: gather row p(q) of W, convert to tf32, swizzle-store.
        const float4* Wg = (const float4*)W;
        #pragma unroll
        for (int i = 0; i < BN / 16; i++) {
            int r = r0 + i * 16;
            int q = bn0 + r;
            uint4 t;
            if (q < P_DIM) {
                int x = q / NYY;
                int y = q - x * NYY;
                int p = y * NXX + x;
                float4 v = Wg[p * 16 + c4];
                t.x = f2tf32(v.x); t.y = f2tf32(v.y);
                t.z = f2tf32(v.z); t.w = f2tf32(v.w);
            } else {
                t.x = t.y = t.z = t.w = 0u;
            }
            int pc4 = c4 ^ (r & 7);
            *(uint4*)&Bsm[r * 64 + pc4 * 4] = t;
        }
    }
    __syncthreads();

    const int warp = tid >> 5;
    const int lane = tid & 31;
    const int wm = (warp & 3) * 32;     // 4 warps along m
    const int wn = (warp >> 2) * 32;    // 2 warps along n
    const int lrow = lane >> 2;         // groupID
    const int lcol = lane & 3;          // threadID_in_group

    float acc[2][4][4];
    #pragma unroll
    for (int i = 0; i < 2; i++)
        #pragma unroll
        for (int j = 0; j < 4; j++)
            #pragma unroll
            for (int k = 0; k < 4; k++) acc[i][j][k] = 0.0f;

    #pragma unroll
    for (int ks = 0; ks < 8; ks++) {
        const int c0 = ks * 2;          // float4-col index of low half of k-block
        uint32_t a[2][4];
        #pragma unroll
        for (int mf = 0; mf < 2; mf++) {
            int ra = wm + mf * 16 + lrow;   // ra&7 == lrow
            int rb = ra + 8;
            a[mf][0] = Asm[ra * 64 + ((c0       ^ lrow) << 2) + lcol];
            a[mf][1] = Asm[rb * 64 + ((c0       ^ lrow) << 2) + lcol];
            a[mf][2] = Asm[ra * 64 + (((c0 + 1) ^ lrow) << 2) + lcol];
            a[mf][3] = Asm[rb * 64 + (((c0 + 1) ^ lrow) << 2) + lcol];
        }
        #pragma unroll
        for (int nf = 0; nf < 4; nf++) {
            int rn = wn + nf * 8 + lrow;    // rn&7 == lrow
            uint32_t b0 = Bsm[rn * 64 + ((c0       ^ lrow) << 2) + lcol];
            uint32_t b1 = Bsm[rn * 64 + (((c0 + 1) ^ lrow) << 2) + lcol];
            #pragma unroll
            for (int mf = 0; mf < 2; mf++) {
                asm volatile(
                    "mma.sync.aligned.m16n8k8.row.col.f32.tf32.tf32.f32 "
                    "{%0,%1,%2,%3}, {%4,%5,%6,%7}, {%8,%9}, {%0,%1,%2,%3};\n"
                    : "+f"(acc[mf][nf][0]), "+f"(acc[mf][nf][1]),
                      "+f"(acc[mf][nf][2]), "+f"(acc[mf][nf][3])
                    : "r"(a[mf][0]), "r"(a[mf][1]), "r"(a[mf][2]), "r"(a[mf][3]),
                      "r"(b0), "r"(b1));
            }
        }
    }

    // Epilogue: gather bias via p(q), add, coalesced float2 stores.
    const int q0 = bn0 + wn + 2 * lcol;
    #pragma unroll
    for (int nf = 0; nf < 4; nf++) {
        int q = q0 + nf * 8;
        if (q < P_DIM) {                 // q even; q+1 <= 5493 is then also valid
            int x0 = q / NYY;
            int y0 = q - x0 * NYY;
            float bq0 = bias[y0 * NXX + x0];
            int q1 = q + 1;
            int x1 = q1 / NYY;
            int y1 = q1 - x1 * NYY;
            float bq1 = bias[y1 * NXX + x1];
            #pragma unroll
            for (int mf = 0; mf < 2; mf++) {
                int grow = bm0 + wm + mf * 16 + lrow;
                float2 v0 = make_float2(acc[mf][nf][0] + bq0, acc[mf][nf][1] + bq1);
                float2 v1 = make_float2(acc[mf][nf][2] + bq0, acc[mf][nf][3] + bq1);
                *(float2*)&out[(size_t)grow * P_DIM + q] = v0;
                *(float2*)&out[(size_t)(grow + 8) * P_DIM + q] = v1;
            }
        }
    }
}

extern "C" void kernel_launch(void* const* d_in, const int* in_sizes, int n_in,
                              void* d_out, int out_size) {
    const float* inputs = (const float*)d_in[0];   // [8192, 64]
    const float* W      = (const float*)d_in[1];   // [5494, 64]
    const float* bias   = (const float*)d_in[2];   // [5494]
    float* out = (float*)d_out;                    // [8192, 82, 67, 1]

    (void)in_sizes; (void)n_in; (void)out_size;

    dim3 grid(NPAD / BN, B_DIM / BM);   // (86, 64)
    gemm_kernel<<<grid, GEMM_THREADS>>>(inputs, W, bias, out);
}

// round 16
// speedup vs baseline: 1.2137x; 1.0210x over previous
#include <cuda_runtime.h>
#include <cstdint>

#define B_DIM 8192
#define F_DIM 64
#define NXX   82
#define NYY   67
#define P_DIM (NXX * NYY)   // 5494
#define NPAD  5504          // 86 * 64

#define BM 128
#define BN 64
#define GEMM_THREADS 256

__device__ __forceinline__ uint32_t f2tf32(float x) {
    uint32_t r;
    asm("cvt.rna.tf32.f32 %0, %1;" : "=r"(r) : "f"(x));
    return r;
}

__device__ __forceinline__ uint32_t smem_u32(const void* p) {
    uint32_t a;
    asm("{ .reg .u64 t; cvta.to.shared.u64 t, %1; cvt.u32.u64 %0, t; }"
        : "=r"(a) : "l"(p));
    return a;
}

__device__ __forceinline__ void ldsm4(uint32_t r[4], uint32_t addr) {
    asm volatile("ldmatrix.sync.aligned.m8n8.x4.shared.b16 {%0,%1,%2,%3}, [%4];"
                 : "=r"(r[0]), "=r"(r[1]), "=r"(r[2]), "=r"(r[3])
                 : "r"(addr));
}

// C[b][q] = sum_f A[b][f] * W[p(q)][f] + bias[p(q)], q = x*67+y, p = y*82+x
// (output transpose folded into the B-row gather; a full 256B W row per tile
// row so gather granularity == load granularity). out [B, 5494] contiguous.
// Block 128x64, K=64 single pass, 8 warps 4(m)x2(n), warp tile 32x32 of
// m16n8k8 tf32. Fragment loads via ldmatrix.x4 (4x fewer l1tex requests).
__global__ __launch_bounds__(GEMM_THREADS, 3)
void gemm_kernel(const float* __restrict__ A, const float* __restrict__ W,
                 const float* __restrict__ bias, float* __restrict__ out) {
    __shared__ __align__(128) uint32_t Asm[BM * 64];   // 32 KB
    __shared__ __align__(128) uint32_t Bsm[BN * 64];   // 16 KB

    const int tid = threadIdx.x;
    const int bn0 = blockIdx.x * BN;   // n fast -> concurrent blocks share A in L2
    const int bm0 = blockIdx.y * BM;

    {
        const int c4 = tid & 15;   // float4 column
        const int r0 = tid >> 4;   // 16 rows per pass
        const float4* Ag = (const float4*)(A + (size_t)bm0 * 64);
        #pragma unroll
        for (int i = 0; i < BM / 16; i++) {
            int r = r0 + i * 16;
            float4 v = Ag[r * 16 + c4];
            int pc4 = c4 ^ (r & 7);
            uint4 t;
            t.x = f2tf32(v.x); t.y = f2tf32(v.y);
            t.z = f2tf32(v.z); t.w = f2tf32(v.w);
            *(uint4*)&Asm[r * 64 + pc4 * 4] = t;
        }
        // B: gather row p(q) of W, convert to tf32, swizzle-store.
        const float4* Wg = (const float4*)W;
        #pragma unroll
        for (int i = 0; i < BN / 16; i++) {
            int r = r0 + i * 16;
            int q = bn0 + r;
            uint4 t;
            if (q < P_DIM) {
                int x = q / NYY;
                int y = q - x * NYY;
                int p = y * NXX + x;
                float4 v = Wg[p * 16 + c4];
                t.x = f2tf32(v.x); t.y = f2tf32(v.y);
                t.z = f2tf32(v.z); t.w = f2tf32(v.w);
            } else {
                t.x = t.y = t.z = t.w = 0u;
            }
            int pc4 = c4 ^ (r & 7);
            *(uint4*)&Bsm[r * 64 + pc4 * 4] = t;
        }
    }
    __syncthreads();

    const int warp = tid >> 5;
    const int lane = tid & 31;
    const int wm = (warp & 3) * 32;     // 4 warps along m
    const int wn = (warp >> 2) * 32;    // 2 warps along n
    const int lrow = lane >> 2;         // groupID
    const int lcol = lane & 3;          // threadID_in_group

    // ldmatrix per-thread bases. Thread group L = lane>>3 serves matrix L:
    //   row-block select = L&1 (rows +0 / +8), k-half select h = L>>1.
    // Stored byte of (row, c4) = row*256 + 16*(c4 ^ (row&7)); row&7 == j.
    // addr(ks) = base ^ (ks<<5), with base = smem + row*256 + (j<<4) ^ (h<<4)
    // (XOR is carry-free: h<<4 is bit4, ks<<5 bits 5..8, j<<4 bits 4..6).
    const int j  = lane & 7;
    const int L  = lane >> 3;
    const int rsel = (L & 1) * 8;
    const uint32_t h16 = (uint32_t)(L >> 1) << 4;
    const uint32_t Asm_s = smem_u32(Asm);
    const uint32_t Bsm_s = smem_u32(Bsm);

    uint32_t a_base[2], b_base[2];
    #pragma unroll
    for (int mf = 0; mf < 2; mf++)
        a_base[mf] = Asm_s + (uint32_t)(wm + mf * 16 + rsel + j) * 256u
                   + (((uint32_t)j << 4) ^ h16);
    #pragma unroll
    for (int p = 0; p < 2; p++)          // nf pairs (0,1) and (2,3)
        b_base[p] = Bsm_s + (uint32_t)(wn + (2 * p + (L & 1)) * 8 + j) * 256u
                  + (((uint32_t)j << 4) ^ h16);

    float acc[2][4][4];
    #pragma unroll
    for (int i = 0; i < 2; i++)
        #pragma unroll
        for (int jj = 0; jj < 4; jj++)
            #pragma unroll
            for (int k = 0; k < 4; k++) acc[i][jj][k] = 0.0f;

    #pragma unroll
    for (int ks = 0; ks < 8; ks++) {
        const uint32_t kx = (uint32_t)ks << 5;
        uint32_t a[2][4];
        ldsm4(a[0], a_base[0] ^ kx);
        ldsm4(a[1], a_base[1] ^ kx);
        uint32_t b01[4], b23[4];
        ldsm4(b01, b_base[0] ^ kx);
        ldsm4(b23, b_base[1] ^ kx);
        // b01: {nf0 klow, nf1 klow, nf0 khigh, nf1 khigh}; b23 same for nf2/3.
        uint32_t bb[4][2];
        bb[0][0] = b01[0]; bb[0][1] = b01[2];
        bb[1][0] = b01[1]; bb[1][1] = b01[3];
        bb[2][0] = b23[0]; bb[2][1] = b23[2];
        bb[3][0] = b23[1]; bb[3][1] = b23[3];
        #pragma unroll
        for (int nf = 0; nf < 4; nf++) {
            #pragma unroll
            for (int mf = 0; mf < 2; mf++) {
                asm volatile(
                    "mma.sync.aligned.m16n8k8.row.col.f32.tf32.tf32.f32 "
                    "{%0,%1,%2,%3}, {%4,%5,%6,%7}, {%8,%9}, {%0,%1,%2,%3};\n"
                    : "+f"(acc[mf][nf][0]), "+f"(acc[mf][nf][1]),
                      "+f"(acc[mf][nf][2]), "+f"(acc[mf][nf][3])
                    : "r"(a[mf][0]), "r"(a[mf][1]), "r"(a[mf][2]), "r"(a[mf][3]),
                      "r"(bb[nf][0]), "r"(bb[nf][1]));
            }
        }
    }

    // Epilogue: gather bias via p(q), add, coalesced float2 stores.
    const int q0 = bn0 + wn + 2 * lcol;
    #pragma unroll
    for (int nf = 0; nf < 4; nf++) {
        int q = q0 + nf * 8;
        if (q < P_DIM) {                 // q even; q+1 is then also < P_DIM
            int x0 = q / NYY;
            int y0 = q - x0 * NYY;
            float bq0 = bias[y0 * NXX + x0];
            int q1 = q + 1;
            int x1 = q1 / NYY;
            int y1 = q1 - x1 * NYY;
            float bq1 = bias[y1 * NXX + x1];
            #pragma unroll
            for (int mf = 0; mf < 2; mf++) {
                int grow = bm0 + wm + mf * 16 + lrow;
                float2 v0 = make_float2(acc[mf][nf][0] + bq0, acc[mf][nf][1] + bq1);
                float2 v1 = make_float2(acc[mf][nf][2] + bq0, acc[mf][nf][3] + bq1);
                *(float2*)&out[(size_t)grow * P_DIM + q] = v0;
                *(float2*)&out[(size_t)(grow + 8) * P_DIM + q] = v1;
            }
        }
    }
}

extern "C" void kernel_launch(void* const* d_in, const int* in_sizes, int n_in,
                              void* d_out, int out_size) {
    const float* inputs = (const float*)d_in[0];   // [8192, 64]
    const float* W      = (const float*)d_in[1];   // [5494, 64]
    const float* bias   = (const float*)d_in[2];   // [5494]
    float* out = (float*)d_out;                    // [8192, 82, 67, 1]

    (void)in_sizes; (void)n_in; (void)out_size;

    dim3 grid(NPAD / BN, B_DIM / BM);   // (86, 64)
    gemm_kernel<<<grid, GEMM_THREADS>>>(inputs, W, bias, out);
}